// round 1
// baseline (speedup 1.0000x reference)
#include <cuda_runtime.h>
#include <cuda_bf16.h>
#include <math_constants.h>

// Problem constants (fixed by setup_inputs: S=4096, B=4, H=2048, E=64, top_k=2)
#define NTOK   16384          // S*B tokens
#define HDIM   2048
#define NEXP   64
#define BM     64             // tokens per CTA
#define BK     32             // K-chunk
#define NCHUNK (HDIM / BK)    // 64

// ---------------------------------------------------------------------------
// Packed fp32x2 FMA (sm_100+). ptxas never auto-fuses this from C++; it is the
// 2x fp32 throughput path on Blackwell.
// ---------------------------------------------------------------------------
__device__ __forceinline__ unsigned long long ffma2(unsigned long long a,
                                                    unsigned long long b,
                                                    unsigned long long c) {
    unsigned long long d;
    asm("fma.rn.f32x2 %0, %1, %2, %3;" : "=l"(d) : "l"(a), "l"(b), "l"(c));
    return d;
}

__device__ __forceinline__ unsigned long long pack_dup(float x) {
    unsigned int u = __float_as_uint(x);
    unsigned long long r;
    asm("mov.b64 %0, {%1, %1};" : "=l"(r) : "r"(u));
    return r;
}

// ---------------------------------------------------------------------------
// GEMM: logits[T, 64] = X[T, 2048] . W[64, 2048]^T    (both K-contiguous)
//
// 64 threads/CTA, each thread computes an 8(m) x 8(n) register tile, with the
// n dimension held as 4 packed f32x2 pairs. Thread coords: ty=tid>>3 (m),
// tx=tid&7 (n). Register tile is STRIDED (m = ty+8j, n-pair p = tx+8p) so all
// shared-memory accesses are bank-conflict-free.
//
// SMEM:
//   Xs2[k][2m(+dup)] : A values stored as duplicated pairs {x,x} so the FFMA2
//                      "a" operand is a single aligned 8B LDS (no packs in the
//                      inner loop). Row stride 130 words (520B, 8B aligned).
//   Ws[k][n]         : B values, n contiguous so an n-pair is one 8B LDS.
//                      Row stride 66 words (264B, 8B aligned).
//
// Global loads for the next chunk are register-staged (prefetched) before the
// compute section so LDG latency overlaps ~2000 cycles of FFMA2 work.
// ---------------------------------------------------------------------------
__global__ __launch_bounds__(64)
void router_gemm_kernel(const float* __restrict__ X,
                        const float* __restrict__ W,
                        float* __restrict__ logits) {
    __shared__ float Xs2[BK][2 * BM + 2];  // stride 130 words
    __shared__ float Ws[BK][NEXP + 2];     // stride 66 words

    const int tid = threadIdx.x;
    const int ty  = tid >> 3;   // 0..7
    const int tx  = tid & 7;    // 0..7
    const int m0  = blockIdx.x * BM;

    // Prefetch chunk 0: each thread loads 8 float4 of X (rows ty+8i, cols 4tx..)
    // and 8 float4 of W. 8 consecutive lanes read 128B contiguous -> coalesced.
    float4 xg[8], wg[8];
    #pragma unroll
    for (int i = 0; i < 8; i++) {
        xg[i] = *(const float4*)&X[(size_t)(m0 + ty + 8 * i) * HDIM + 4 * tx];
        wg[i] = *(const float4*)&W[(size_t)(ty + 8 * i) * HDIM + 4 * tx];
    }

    unsigned long long acc[8][4];
    #pragma unroll
    for (int j = 0; j < 8; j++)
        #pragma unroll
        for (int p = 0; p < 4; p++) acc[j][p] = 0ull;

    for (int c = 0; c < NCHUNK; c++) {
        __syncthreads();  // previous compute done reading smem
        #pragma unroll
        for (int i = 0; i < 8; i++) {
            const int m = ty + 8 * i;   // X row / W row (expert) within tile
            // A: duplicated pairs, 8B stores (conflict-free: bank = lr+4*lc+const)
            *(unsigned long long*)&Xs2[4 * tx + 0][2 * m] = pack_dup(xg[i].x);
            *(unsigned long long*)&Xs2[4 * tx + 1][2 * m] = pack_dup(xg[i].y);
            *(unsigned long long*)&Xs2[4 * tx + 2][2 * m] = pack_dup(xg[i].z);
            *(unsigned long long*)&Xs2[4 * tx + 3][2 * m] = pack_dup(xg[i].w);
            // B: transpose to [k][n] (n contiguous); benign 2-way store conflict
            Ws[4 * tx + 0][m] = wg[i].x;
            Ws[4 * tx + 1][m] = wg[i].y;
            Ws[4 * tx + 2][m] = wg[i].z;
            Ws[4 * tx + 3][m] = wg[i].w;
        }
        __syncthreads();

        // Prefetch next chunk while computing this one
        if (c + 1 < NCHUNK) {
            const int k0 = (c + 1) * BK;
            #pragma unroll
            for (int i = 0; i < 8; i++) {
                xg[i] = *(const float4*)&X[(size_t)(m0 + ty + 8 * i) * HDIM + k0 + 4 * tx];
                wg[i] = *(const float4*)&W[(size_t)(ty + 8 * i) * HDIM + k0 + 4 * tx];
            }
        }

        #pragma unroll 8
        for (int k = 0; k < BK; k++) {
            unsigned long long a2[8], b2[4];
            #pragma unroll
            for (int j = 0; j < 8; j++)   // {x,x} pairs, bank = 2k+2ty+const
                a2[j] = *(const unsigned long long*)&Xs2[k][2 * (ty + 8 * j)];
            #pragma unroll
            for (int p = 0; p < 4; p++)   // {w[2n],w[2n+1]}, bank = 2k+2tx+const
                b2[p] = *(const unsigned long long*)&Ws[k][2 * (tx + 8 * p)];
            #pragma unroll
            for (int j = 0; j < 8; j++)
                #pragma unroll
                for (int p = 0; p < 4; p++)
                    acc[j][p] = ffma2(a2[j], b2[p], acc[j][p]);
        }
    }

    // Epilogue: acc pair == two consecutive logits -> single 8B store each.
    #pragma unroll
    for (int j = 0; j < 8; j++) {
        const size_t row = (size_t)(m0 + ty + 8 * j);
        #pragma unroll
        for (int p = 0; p < 4; p++)
            *(unsigned long long*)&logits[row * NEXP + 2 * (tx + 8 * p)] = acc[j][p];
    }
}

// ---------------------------------------------------------------------------
// Per-token softmax (fp32) + top-2 indices over raw logits.
// One warp per token; each lane owns logits[2*lane], logits[2*lane+1].
// Argmax tie-break: lowest index first (matches jax.lax.top_k).
// ---------------------------------------------------------------------------
__global__ void softmax_topk_kernel(const float* __restrict__ logits,
                                    float* __restrict__ aff,
                                    float* __restrict__ idxf) {
    const int gw   = (int)((blockIdx.x * blockDim.x + threadIdx.x) >> 5);
    const int lane = threadIdx.x & 31;
    if (gw >= NTOK) return;

    const float2 v = *(const float2*)&logits[(size_t)gw * NEXP + 2 * lane];

    // top-1 (value, index) with lowest-index tie-break
    float mv; int mi;
    if (v.y > v.x) { mv = v.y; mi = 2 * lane + 1; } else { mv = v.x; mi = 2 * lane; }
    #pragma unroll
    for (int off = 16; off; off >>= 1) {
        float ov = __shfl_xor_sync(0xffffffffu, mv, off);
        int   oi = __shfl_xor_sync(0xffffffffu, mi, off);
        if (ov > mv || (ov == mv && oi < mi)) { mv = ov; mi = oi; }
    }

    // softmax in fp32 (max-subtracted, like jax.nn.softmax)
    const float e0 = expf(v.x - mv);
    const float e1 = expf(v.y - mv);
    float s = e0 + e1;
    #pragma unroll
    for (int off = 16; off; off >>= 1) s += __shfl_xor_sync(0xffffffffu, s, off);
    const float inv = 1.0f / s;
    *(float2*)&aff[(size_t)gw * NEXP + 2 * lane] = make_float2(e0 * inv, e1 * inv);

    // top-2: mask out top-1's slot, reduce again
    const float v0 = (2 * lane     == mi) ? -CUDART_INF_F : v.x;
    const float v1 = (2 * lane + 1 == mi) ? -CUDART_INF_F : v.y;
    float sv; int si;
    if (v1 > v0) { sv = v1; si = 2 * lane + 1; } else { sv = v0; si = 2 * lane; }
    #pragma unroll
    for (int off = 16; off; off >>= 1) {
        float ov = __shfl_xor_sync(0xffffffffu, sv, off);
        int   oi = __shfl_xor_sync(0xffffffffu, si, off);
        if (ov > sv || (ov == sv && oi < si)) { sv = ov; si = oi; }
    }

    if (lane == 0) {
        idxf[2 * (size_t)gw + 0] = (float)mi;
        idxf[2 * (size_t)gw + 1] = (float)si;
    }
}

// ---------------------------------------------------------------------------
// d_out layout (fp32, return order, flattened + concatenated):
//   [0,               T*E)   router_logits
//   [T*E,           2*T*E)   expert_affinities
//   [2*T*E, 2*T*E + 2*T)     expert_index (int values as float)
// ---------------------------------------------------------------------------
extern "C" void kernel_launch(void* const* d_in, const int* in_sizes, int n_in,
                              void* d_out, int out_size) {
    (void)in_sizes; (void)n_in; (void)out_size;
    const float* X = (const float*)d_in[0];   // (S,B,H) = (T, 2048)
    const float* W = (const float*)d_in[1];   // (E, H)  = (64, 2048)
    float* out    = (float*)d_out;
    float* logits = out;
    float* aff    = out + (size_t)NTOK * NEXP;
    float* idxf   = out + 2 * (size_t)NTOK * NEXP;

    router_gemm_kernel<<<NTOK / BM, 64>>>(X, W, logits);

    const int warps_per_block = 8;  // 256 threads
    softmax_topk_kernel<<<NTOK / warps_per_block, warps_per_block * 32>>>(logits, aff, idxf);
}